// round 15
// baseline (speedup 1.0000x reference)
#include <cuda_runtime.h>
#include <cuda_bf16.h>

constexpr int Bb  = 2048;
constexpr int Tt  = 20;
constexpr int Mm  = 16384;
constexpr int HS  = 128;
constexpr int G3  = 384;
constexpr int RT  = Mm * Tt;        // 327680
constexpr int OUT0 = Mm * 64;

__device__ float g_gi[(size_t)RT * G3];
__device__ float g_ys[(size_t)RT * HS];

typedef unsigned long long ULL;

__device__ __forceinline__ float sigm(float x) { return 1.0f / (1.0f + __expf(-x)); }
__device__ __forceinline__ float tanh_(float x) { return 1.0f - 2.0f / (__expf(2.0f * x) + 1.0f); }

__device__ __forceinline__ unsigned smem_u32(const void* p) {
    unsigned a;
    asm("{ .reg .u64 t; cvta.to.shared.u64 t, %1; cvt.u32.u64 %0, t; }" : "=r"(a) : "l"(p));
    return a;
}
__device__ __forceinline__ void ldsm4(unsigned* r, unsigned addr) {
    asm volatile("ldmatrix.sync.aligned.m8n8.x4.shared.b16 {%0,%1,%2,%3}, [%4];"
        : "=r"(r[0]), "=r"(r[1]), "=r"(r[2]), "=r"(r[3]) : "r"(addr));
}
__device__ __forceinline__ void mma16816(float* c, const unsigned* a, unsigned b0, unsigned b1) {
    asm volatile("mma.sync.aligned.m16n8k16.row.col.f32.bf16.bf16.f32 "
        "{%0,%1,%2,%3}, {%4,%5,%6,%7}, {%8,%9}, {%0,%1,%2,%3};"
        : "+f"(c[0]), "+f"(c[1]), "+f"(c[2]), "+f"(c[3])
        : "r"(a[0]), "r"(a[1]), "r"(a[2]), "r"(a[3]), "r"(b0), "r"(b1));
}

__device__ __forceinline__ void split4(float4 v, ULL& hi, ULL& lo) {
    float a[4] = {v.x, v.y, v.z, v.w};
    unsigned short hs[4], ls[4];
#pragma unroll
    for (int i = 0; i < 4; ++i) {
        __nv_bfloat16 h = __float2bfloat16(a[i]);
        hs[i] = ((__nv_bfloat16_raw)h).x;
        __nv_bfloat16 l = __float2bfloat16(a[i] - __bfloat162float(h));
        ls[i] = ((__nv_bfloat16_raw)l).x;
    }
    hi = (ULL)hs[0] | ((ULL)hs[1] << 16) | ((ULL)hs[2] << 32) | ((ULL)hs[3] << 48);
    lo = (ULL)ls[0] | ((ULL)ls[1] << 16) | ((ULL)ls[2] << 32) | ((ULL)ls[3] << 48);
}
__device__ __forceinline__ unsigned split1(float x, unsigned short& lo) {
    __nv_bfloat16 h = __float2bfloat16(x);
    lo = ((__nv_bfloat16_raw)__float2bfloat16(x - __bfloat162float(h))).x;
    return ((__nv_bfloat16_raw)h).x;
}

// ---------------------------------------------------------------------------
// HMMA gi GEMM (layers 1,2) — verified R12/R13 kernel, unchanged.
// ---------------------------------------------------------------------------
constexpr int PAB = 272;
constexpr int AH0 = 0, AL0 = 34816, BH0 = 69632, BL0 = 121856;
constexpr int SMEM_MMA = 174080;

__global__ __launch_bounds__(512) void gi_mma(
    const float* __restrict__ W, const float* __restrict__ bih)
{
    extern __shared__ char smc[];
    unsigned sb = smem_u32(smc);
    int tid = threadIdx.x, warp = tid >> 5, lane = tid & 31;
    size_t row0 = (size_t)blockIdx.x * 128;

    for (int idx = tid; idx < 128 * 32; idx += 512) {
        int r = idx >> 5, k4 = (idx & 31) * 4;
        float4 v = *(const float4*)(g_ys + (row0 + r) * HS + k4);
        ULL hi, lo; split4(v, hi, lo);
        int off = r * PAB + k4 * 2;
        *(ULL*)(smc + AH0 + off) = hi;
        *(ULL*)(smc + AL0 + off) = lo;
    }

    int m0  = (warp >> 2) * 32;
    int n0w = (warp & 3) * 48;
    unsigned aoff = sb + (unsigned)((m0 + (lane & 7) + ((lane & 8) ? 8 : 0)) * PAB
                                    + ((lane & 16) ? 16 : 0));
    unsigned boff = sb + (unsigned)(BH0 + (n0w + (lane & 7) + ((lane & 8) ? 8 : 0)) * PAB
                                    + ((lane & 16) ? 16 : 0));

    for (int ch = 0; ch < 2; ++ch) {
        __syncthreads();
        for (int idx = tid; idx < 192 * 32; idx += 512) {
            int gg = idx >> 5, k4 = (idx & 31) * 4;
            float4 v = *(const float4*)(W + (size_t)(ch * 192 + gg) * HS + k4);
            ULL hi, lo; split4(v, hi, lo);
            int off = gg * PAB + k4 * 2;
            *(ULL*)(smc + BH0 + off) = hi;
            *(ULL*)(smc + BL0 + off) = lo;
        }
        __syncthreads();

        float acc[2][6][4];
#pragma unroll
        for (int rt = 0; rt < 2; ++rt)
#pragma unroll
            for (int nt = 0; nt < 6; ++nt)
#pragma unroll
                for (int q = 0; q < 4; ++q) acc[rt][nt][q] = 0.0f;

        for (int ks = 0; ks < 8; ++ks) {
            unsigned ah0[4], al0[4], ah1[4], al1[4];
            unsigned ka = aoff + ks * 32;
            ldsm4(ah0, ka);
            ldsm4(al0, ka + AL0);
            ldsm4(ah1, ka + 16 * PAB);
            ldsm4(al1, ka + 16 * PAB + AL0);
#pragma unroll
            for (int p = 0; p < 3; ++p) {
                unsigned bh[4], bl[4];
                unsigned kb = boff + p * 16 * PAB + ks * 32;
                ldsm4(bh, kb);
                ldsm4(bl, kb + (BL0 - BH0));
                mma16816(acc[0][2*p],   ah0, bh[0], bh[2]);
                mma16816(acc[0][2*p],   ah0, bl[0], bl[2]);
                mma16816(acc[0][2*p],   al0, bh[0], bh[2]);
                mma16816(acc[0][2*p+1], ah0, bh[1], bh[3]);
                mma16816(acc[0][2*p+1], ah0, bl[1], bl[3]);
                mma16816(acc[0][2*p+1], al0, bh[1], bh[3]);
                mma16816(acc[1][2*p],   ah1, bh[0], bh[2]);
                mma16816(acc[1][2*p],   ah1, bl[0], bl[2]);
                mma16816(acc[1][2*p],   al1, bh[0], bh[2]);
                mma16816(acc[1][2*p+1], ah1, bh[1], bh[3]);
                mma16816(acc[1][2*p+1], ah1, bl[1], bl[3]);
                mma16816(acc[1][2*p+1], al1, bh[1], bh[3]);
            }
        }

        int gb = ch * 192 + n0w;
        size_t rA = row0 + m0 + (lane >> 2);
#pragma unroll
        for (int rt = 0; rt < 2; ++rt) {
#pragma unroll
            for (int nt = 0; nt < 6; ++nt) {
                int col = gb + nt * 8 + (lane & 3) * 2;
                float2 bv = *(const float2*)(bih + col);
                float* p0 = g_gi + (rA + rt * 16) * G3 + col;
                *(float2*)p0 = make_float2(acc[rt][nt][0] + bv.x, acc[rt][nt][1] + bv.y);
                *(float2*)(p0 + 8 * G3) =
                    make_float2(acc[rt][nt][2] + bv.x, acc[rt][nt][3] + bv.y);
            }
        }
    }
}

// ---------------------------------------------------------------------------
// HMMA gi GEMM layer 0 (K=64, embedding fused into the A fill).
// 2560 CTAs x 512 thr, 128 rows/CTA. Pitch 144B (144 % 128 = 16 -> the 8
// ldmatrix rows hit distinct 16B banks: conflict-free). A and full B resident.
// smem: Ah@0 (128x144) | Al@18432 | Bh@36864 (384x144) | Bl@92160. 147456 B.
// ---------------------------------------------------------------------------
constexpr int P64 = 144;
constexpr int A64L = 18432, B64H = 36864, B64L = 92160;
constexpr int SMEM_M64 = 147456;

__global__ __launch_bounds__(512) void gi_mma64(
    const float* __restrict__ Wih, const float* __restrict__ bih,
    const float* __restrict__ x,   const float* __restrict__ pea,
    const float* __restrict__ pet, const float* __restrict__ embW,
    const float* __restrict__ embB)
{
    extern __shared__ char smc[];
    unsigned sb = smem_u32(smc);
    int tid = threadIdx.x, warp = tid >> 5, lane = tid & 31;
    size_t row0 = (size_t)blockIdx.x * 128;

    // A fill: embedding computed inline, split to bf16 hi/lo
    for (int idx = tid; idx < 128 * 16; idx += 512) {
        int r = idx >> 4, kq = idx & 15;
        int row = (int)row0 + r;
        int t = row % Tt;
        int n = (row / Tt) & 7;
        float pe = __ldg(pet + t) + __ldg(pea + n);
        float2 xv = *(const float2*)(x + (size_t)row * 2);
        float x0 = xv.x + pe, x1 = xv.y + pe;
        float4 w0 = __ldg((const float4*)(embW + 8 * kq));
        float4 w1 = __ldg((const float4*)(embW + 8 * kq + 4));
        float4 b4 = __ldg((const float4*)(embB + 4 * kq));
        float4 v;
        v.x = fmaxf(fmaf(x0, w0.x, fmaf(x1, w0.y, b4.x)), 0.0f);
        v.y = fmaxf(fmaf(x0, w0.z, fmaf(x1, w0.w, b4.y)), 0.0f);
        v.z = fmaxf(fmaf(x0, w1.x, fmaf(x1, w1.y, b4.z)), 0.0f);
        v.w = fmaxf(fmaf(x0, w1.z, fmaf(x1, w1.w, b4.w)), 0.0f);
        ULL hi, lo; split4(v, hi, lo);
        int off = r * P64 + kq * 8;
        *(ULL*)(smc + off) = hi;
        *(ULL*)(smc + A64L + off) = lo;
    }
    // B fill: Wih0 (384 x 64)
    for (int idx = tid; idx < 384 * 16; idx += 512) {
        int g = idx >> 4, kq = idx & 15;
        float4 v = *(const float4*)(Wih + (size_t)g * 64 + kq * 4);
        ULL hi, lo; split4(v, hi, lo);
        int off = g * P64 + kq * 8;
        *(ULL*)(smc + B64H + off) = hi;
        *(ULL*)(smc + B64L + off) = lo;
    }
    __syncthreads();

    int m0  = (warp >> 2) * 32;
    int n0w = (warp & 3) * 48;
    int lr  = (lane & 7) + ((lane & 8) ? 8 : 0);
    unsigned lo16 = (lane & 16) ? 16u : 0u;
    unsigned aoff = sb + (unsigned)((m0 + lr) * P64) + lo16;
    unsigned boff = sb + (unsigned)(B64H + (n0w + lr) * P64) + lo16;

    for (int ch = 0; ch < 2; ++ch) {
        float acc[2][6][4];
#pragma unroll
        for (int rt = 0; rt < 2; ++rt)
#pragma unroll
            for (int nt = 0; nt < 6; ++nt)
#pragma unroll
                for (int q = 0; q < 4; ++q) acc[rt][nt][q] = 0.0f;

#pragma unroll
        for (int ks = 0; ks < 4; ++ks) {
            unsigned ah0[4], al0[4], ah1[4], al1[4];
            unsigned ka = aoff + ks * 32;
            ldsm4(ah0, ka);
            ldsm4(al0, ka + A64L);
            ldsm4(ah1, ka + 16 * P64);
            ldsm4(al1, ka + 16 * P64 + A64L);
#pragma unroll
            for (int p = 0; p < 3; ++p) {
                unsigned bh[4], bl[4];
                unsigned kb = boff + (unsigned)(ch * 192 * P64 + p * 16 * P64) + ks * 32;
                ldsm4(bh, kb);
                ldsm4(bl, kb + (B64L - B64H));
                mma16816(acc[0][2*p],   ah0, bh[0], bh[2]);
                mma16816(acc[0][2*p],   ah0, bl[0], bl[2]);
                mma16816(acc[0][2*p],   al0, bh[0], bh[2]);
                mma16816(acc[0][2*p+1], ah0, bh[1], bh[3]);
                mma16816(acc[0][2*p+1], ah0, bl[1], bl[3]);
                mma16816(acc[0][2*p+1], al0, bh[1], bh[3]);
                mma16816(acc[1][2*p],   ah1, bh[0], bh[2]);
                mma16816(acc[1][2*p],   ah1, bl[0], bl[2]);
                mma16816(acc[1][2*p],   al1, bh[0], bh[2]);
                mma16816(acc[1][2*p+1], ah1, bh[1], bh[3]);
                mma16816(acc[1][2*p+1], ah1, bl[1], bl[3]);
                mma16816(acc[1][2*p+1], al1, bh[1], bh[3]);
            }
        }

        int gb = ch * 192 + n0w;
        size_t rA = row0 + m0 + (lane >> 2);
#pragma unroll
        for (int rt = 0; rt < 2; ++rt) {
#pragma unroll
            for (int nt = 0; nt < 6; ++nt) {
                int col = gb + nt * 8 + (lane & 3) * 2;
                float2 bv = *(const float2*)(bih + col);
                float* p0 = g_gi + (rA + rt * 16) * G3 + col;
                *(float2*)p0 = make_float2(acc[rt][nt][0] + bv.x, acc[rt][nt][1] + bv.y);
                *(float2*)(p0 + 8 * G3) =
                    make_float2(acc[rt][nt][2] + bv.x, acc[rt][nt][3] + bv.y);
            }
        }
    }
}

// ---------------------------------------------------------------------------
// HMMA GRU scan v3: R14 kernel + gi prefetch hoisted before the k-loop
// (gi loads are h-independent; DRAM latency hides behind the MMA work).
// ---------------------------------------------------------------------------
constexpr int WH0 = 0, WL0 = 98304, HH0 = 196608, HDL = 17408;
constexpr int SMEM_SCM = 231424;

__global__ __launch_bounds__(512) void scan_mma(
    const float* __restrict__ Whh, const float* __restrict__ bhh,
    float* __restrict__ hid)
{
    extern __shared__ char smc[];
    unsigned sb = smem_u32(smc);
    int tid = threadIdx.x, warp = tid >> 5, lane = tid & 31;
    int m0 = blockIdx.x * 64;

    for (int idx = tid; idx < 384 * 16; idx += 512) {
        int g = idx >> 4, c = idx & 15;
        const float* src = Whh + (size_t)g * HS + c * 8;
        float4 v0 = *(const float4*)(src);
        float4 v1 = *(const float4*)(src + 4);
        ULL h0, l0, h1, l1;
        split4(v0, h0, l0);
        split4(v1, h1, l1);
        int sw = g * 256 + ((c ^ (g & 7)) << 4);
        *(ULL*)(smc + WH0 + sw)     = h0;
        *(ULL*)(smc + WH0 + sw + 8) = h1;
        *(ULL*)(smc + WL0 + sw)     = l0;
        *(ULL*)(smc + WL0 + sw + 8) = l1;
    }
    for (int i = tid; i < 8704; i += 512) ((unsigned*)(smc + HH0))[i] = 0u;

    int rh2 = warp >> 3;
    int wg  = warp & 7;
    int lr   = (lane & 7) + ((lane & 8) ? 8 : 0);
    int c0   = (lane & 16) ? 1 : 0;
    unsigned abase = sb + (unsigned)(HH0 + (rh2 * 32 + lr) * PAB + c0 * 16);
    int grow = wg * 16 + lr;
    unsigned bRow = sb + (unsigned)(grow * 256);
    int rx = grow & 7;

    int cq = (lane & 3) * 2;
    int rq = lane >> 2;

    float2 biR[2], biZ[2], biN[2];
#pragma unroll
    for (int nt = 0; nt < 2; ++nt) {
        int c = wg * 16 + nt * 8 + cq;
        biR[nt] = *(const float2*)(bhh + c);
        biZ[nt] = *(const float2*)(bhh + 128 + c);
        biN[nt] = *(const float2*)(bhh + 256 + c);
    }

    float2 hreg[2][2][2];
#pragma unroll
    for (int a = 0; a < 2; ++a)
#pragma unroll
        for (int b = 0; b < 2; ++b)
#pragma unroll
            for (int c = 0; c < 2; ++c) hreg[a][b][c] = make_float2(0.0f, 0.0f);

    __syncthreads();

    for (int t = 0; t < Tt; ++t) {
        // gi prefetch (independent of h) — overlaps the MMA loop below
        float2 giR[2][2][2], giZ[2][2][2], giN[2][2][2];
#pragma unroll
        for (int mt = 0; mt < 2; ++mt)
#pragma unroll
        for (int rh = 0; rh < 2; ++rh)
#pragma unroll
        for (int nt = 0; nt < 2; ++nt) {
            int m = rh2 * 32 + mt * 16 + rh * 8 + rq;
            int c = wg * 16 + nt * 8 + cq;
            const float* gp = g_gi + ((size_t)(m0 + m) * Tt + t) * G3;
            giR[mt][rh][nt] = *(const float2*)(gp + c);
            giZ[mt][rh][nt] = *(const float2*)(gp + 128 + c);
            giN[mt][rh][nt] = *(const float2*)(gp + 256 + c);
        }

        float acc[2][3][2][4];
#pragma unroll
        for (int a = 0; a < 2; ++a)
#pragma unroll
            for (int s = 0; s < 3; ++s)
#pragma unroll
                for (int n = 0; n < 2; ++n)
#pragma unroll
                    for (int q = 0; q < 4; ++q) acc[a][s][n][q] = 0.0f;

        for (int ks = 0; ks < 8; ++ks) {
            unsigned ka = abase + ks * 32;
            unsigned ah0[4], al0[4], ah1[4], al1[4];
            ldsm4(ah0, ka);
            ldsm4(al0, ka + HDL);
            ldsm4(ah1, ka + 16 * PAB);
            ldsm4(al1, ka + 16 * PAB + HDL);
            unsigned ch = (unsigned)(((2 * ks + c0) ^ rx) << 4);
#pragma unroll
            for (int s = 0; s < 3; ++s) {
                unsigned kb = bRow + (unsigned)(s * 128 * 256) + ch;
                unsigned bh[4], bl[4];
                ldsm4(bh, kb);
                ldsm4(bl, kb + (unsigned)WL0);
                mma16816(acc[0][s][0], ah0, bh[0], bh[2]);
                mma16816(acc[0][s][0], ah0, bl[0], bl[2]);
                mma16816(acc[0][s][0], al0, bh[0], bh[2]);
                mma16816(acc[0][s][1], ah0, bh[1], bh[3]);
                mma16816(acc[0][s][1], ah0, bl[1], bl[3]);
                mma16816(acc[0][s][1], al0, bh[1], bh[3]);
                mma16816(acc[1][s][0], ah1, bh[0], bh[2]);
                mma16816(acc[1][s][0], ah1, bl[0], bl[2]);
                mma16816(acc[1][s][0], al1, bh[0], bh[2]);
                mma16816(acc[1][s][1], ah1, bh[1], bh[3]);
                mma16816(acc[1][s][1], ah1, bl[1], bl[3]);
                mma16816(acc[1][s][1], al1, bh[1], bh[3]);
            }
        }
        __syncthreads();

#pragma unroll
        for (int mt = 0; mt < 2; ++mt)
#pragma unroll
        for (int rh = 0; rh < 2; ++rh)
#pragma unroll
        for (int nt = 0; nt < 2; ++nt) {
            int m = rh2 * 32 + mt * 16 + rh * 8 + rq;
            int c = wg * 16 + nt * 8 + cq;
            size_t rbase = (size_t)(m0 + m) * Tt + t;
            float ghR0 = acc[mt][0][nt][rh*2], ghR1 = acc[mt][0][nt][rh*2+1];
            float ghZ0 = acc[mt][1][nt][rh*2], ghZ1 = acc[mt][1][nt][rh*2+1];
            float ghN0 = acc[mt][2][nt][rh*2], ghN1 = acc[mt][2][nt][rh*2+1];
            float rv0 = sigm(giR[mt][rh][nt].x + ghR0 + biR[nt].x);
            float rv1 = sigm(giR[mt][rh][nt].y + ghR1 + biR[nt].y);
            float zv0 = sigm(giZ[mt][rh][nt].x + ghZ0 + biZ[nt].x);
            float zv1 = sigm(giZ[mt][rh][nt].y + ghZ1 + biZ[nt].y);
            float nv0 = tanh_(giN[mt][rh][nt].x + rv0 * (ghN0 + biN[nt].x));
            float nv1 = tanh_(giN[mt][rh][nt].y + rv1 * (ghN1 + biN[nt].y));
            float hn0 = (1.0f - zv0) * nv0 + zv0 * hreg[mt][rh][nt].x;
            float hn1 = (1.0f - zv1) * nv1 + zv1 * hreg[mt][rh][nt].y;
            hreg[mt][rh][nt] = make_float2(hn0, hn1);
            *(float2*)(g_ys + rbase * HS + c) = hreg[mt][rh][nt];
            unsigned short l0v, l1v;
            unsigned short h0v = split1(hn0, l0v);
            unsigned short h1v = split1(hn1, l1v);
            int off = m * PAB + c * 2;
            *(unsigned*)(smc + HH0 + off)       = (unsigned)h0v | ((unsigned)h1v << 16);
            *(unsigned*)(smc + HH0 + HDL + off) = (unsigned)l0v | ((unsigned)l1v << 16);
        }
        __syncthreads();
    }

    if (rq == 7) {
#pragma unroll
        for (int mt = 0; mt < 2; ++mt)
#pragma unroll
        for (int rh = 0; rh < 2; ++rh)
#pragma unroll
        for (int nt = 0; nt < 2; ++nt) {
            int m = rh2 * 32 + mt * 16 + rh * 8 + 7;
            int b = (m0 + m) >> 3;
            int c = wg * 16 + nt * 8 + cq;
            *(float2*)(hid + (size_t)b * HS + c) = hreg[mt][rh][nt];
        }
    }
}

// ---------------------------------------------------------------------------
__global__ __launch_bounds__(256) void out_kernel(
    const float* __restrict__ oW, const float* __restrict__ ob,
    float* __restrict__ out)
{
    __shared__ float sW[128 * 64];
    int tid = threadIdx.x;
    for (int idx = tid; idx < 64 * 128; idx += 256) {
        int e = idx >> 7, k = idx & 127;
        sW[k * 64 + e] = oW[idx];
    }
    __syncthreads();
    int gid = blockIdx.x * 256 + tid;
    int e = gid & 63;
    int m = gid >> 6;
    const float* ys = g_ys + ((size_t)m * Tt + (Tt - 1)) * HS;
    float acc = ob[e];
#pragma unroll 8
    for (int k = 0; k < 128; ++k) acc = fmaf(ys[k], sW[k * 64 + e], acc);
    out[gid] = acc;
}

// ---------------------------------------------------------------------------
extern "C" void kernel_launch(void* const* d_in, const int* in_sizes, int n_in,
                              void* d_out, int out_size) {
    const float* x    = (const float*)d_in[0];
    const float* pea  = (const float*)d_in[1];
    const float* pet  = (const float*)d_in[2];
    const float* embW = (const float*)d_in[3];
    const float* embB = (const float*)d_in[4];
    const float* Wih0 = (const float*)d_in[5];
    const float* WihR = (const float*)d_in[6];
    const float* Whh  = (const float*)d_in[7];
    const float* bih  = (const float*)d_in[8];
    const float* bhh  = (const float*)d_in[9];
    const float* outW = (const float*)d_in[10];
    const float* outB = (const float*)d_in[11];

    float* out = (float*)d_out;
    float* hid = out + OUT0;

    cudaFuncSetAttribute(gi_mma64, cudaFuncAttributeMaxDynamicSharedMemorySize, SMEM_M64);
    cudaFuncSetAttribute(gi_mma,   cudaFuncAttributeMaxDynamicSharedMemorySize, SMEM_MMA);
    cudaFuncSetAttribute(scan_mma, cudaFuncAttributeMaxDynamicSharedMemorySize, SMEM_SCM);

    gi_mma64<<<RT / 128, 512, SMEM_M64>>>(Wih0, bih, x, pea, pet, embW, embB);
    scan_mma<<<Mm / 64, 512, SMEM_SCM>>>(Whh, bhh, hid);

    gi_mma<<<RT / 128, 512, SMEM_MMA>>>(WihR, bih + G3);
    scan_mma<<<Mm / 64, 512, SMEM_SCM>>>(Whh + (size_t)G3 * HS, bhh + G3,
                                         hid + (size_t)Bb * HS);

    gi_mma<<<RT / 128, 512, SMEM_MMA>>>(WihR + (size_t)G3 * HS, bih + 2 * G3);
    scan_mma<<<Mm / 64, 512, SMEM_SCM>>>(Whh + (size_t)2 * G3 * HS, bhh + 2 * G3,
                                         hid + (size_t)2 * Bb * HS);

    out_kernel<<<(Mm * 64) / 256, 256>>>(outW, outB, out);
}

// round 16
// speedup vs baseline: 1.2683x; 1.2683x over previous
#include <cuda_runtime.h>
#include <cuda_bf16.h>

constexpr int Bb  = 2048;
constexpr int Tt  = 20;
constexpr int Mm  = 16384;
constexpr int HS  = 128;
constexpr int G3  = 384;
constexpr int RT  = Mm * Tt;        // 327680
constexpr int OUT0 = Mm * 64;

__device__ float g_gi[(size_t)RT * G3];
__device__ float g_ys[(size_t)RT * HS];

typedef unsigned long long ULL;

__device__ __forceinline__ float sigm(float x) { return 1.0f / (1.0f + __expf(-x)); }
__device__ __forceinline__ float tanh_(float x) { return 1.0f - 2.0f / (__expf(2.0f * x) + 1.0f); }

__device__ __forceinline__ unsigned smem_u32(const void* p) {
    unsigned a;
    asm("{ .reg .u64 t; cvta.to.shared.u64 t, %1; cvt.u32.u64 %0, t; }" : "=r"(a) : "l"(p));
    return a;
}
__device__ __forceinline__ void ldsm4(unsigned* r, unsigned addr) {
    asm volatile("ldmatrix.sync.aligned.m8n8.x4.shared.b16 {%0,%1,%2,%3}, [%4];"
        : "=r"(r[0]), "=r"(r[1]), "=r"(r[2]), "=r"(r[3]) : "r"(addr));
}
__device__ __forceinline__ void mma16816(float* c, const unsigned* a, unsigned b0, unsigned b1) {
    asm volatile("mma.sync.aligned.m16n8k16.row.col.f32.bf16.bf16.f32 "
        "{%0,%1,%2,%3}, {%4,%5,%6,%7}, {%8,%9}, {%0,%1,%2,%3};"
        : "+f"(c[0]), "+f"(c[1]), "+f"(c[2]), "+f"(c[3])
        : "r"(a[0]), "r"(a[1]), "r"(a[2]), "r"(a[3]), "r"(b0), "r"(b1));
}

__device__ __forceinline__ void split4(float4 v, ULL& hi, ULL& lo) {
    float a[4] = {v.x, v.y, v.z, v.w};
    unsigned short hs[4], ls[4];
#pragma unroll
    for (int i = 0; i < 4; ++i) {
        __nv_bfloat16 h = __float2bfloat16(a[i]);
        hs[i] = ((__nv_bfloat16_raw)h).x;
        __nv_bfloat16 l = __float2bfloat16(a[i] - __bfloat162float(h));
        ls[i] = ((__nv_bfloat16_raw)l).x;
    }
    hi = (ULL)hs[0] | ((ULL)hs[1] << 16) | ((ULL)hs[2] << 32) | ((ULL)hs[3] << 48);
    lo = (ULL)ls[0] | ((ULL)ls[1] << 16) | ((ULL)ls[2] << 32) | ((ULL)ls[3] << 48);
}
__device__ __forceinline__ unsigned split1(float x, unsigned short& lo) {
    __nv_bfloat16 h = __float2bfloat16(x);
    lo = ((__nv_bfloat16_raw)__float2bfloat16(x - __bfloat162float(h))).x;
    return ((__nv_bfloat16_raw)h).x;
}

// ---------------------------------------------------------------------------
// HMMA gi GEMM (layers 1,2) — verified R12/R13 kernel, unchanged.
// ---------------------------------------------------------------------------
constexpr int PAB = 272;
constexpr int AH0 = 0, AL0 = 34816, BH0 = 69632, BL0 = 121856;
constexpr int SMEM_MMA = 174080;

__global__ __launch_bounds__(512) void gi_mma(
    const float* __restrict__ W, const float* __restrict__ bih)
{
    extern __shared__ char smc[];
    unsigned sb = smem_u32(smc);
    int tid = threadIdx.x, warp = tid >> 5, lane = tid & 31;
    size_t row0 = (size_t)blockIdx.x * 128;

    for (int idx = tid; idx < 128 * 32; idx += 512) {
        int r = idx >> 5, k4 = (idx & 31) * 4;
        float4 v = *(const float4*)(g_ys + (row0 + r) * HS + k4);
        ULL hi, lo; split4(v, hi, lo);
        int off = r * PAB + k4 * 2;
        *(ULL*)(smc + AH0 + off) = hi;
        *(ULL*)(smc + AL0 + off) = lo;
    }

    int m0  = (warp >> 2) * 32;
    int n0w = (warp & 3) * 48;
    unsigned aoff = sb + (unsigned)((m0 + (lane & 7) + ((lane & 8) ? 8 : 0)) * PAB
                                    + ((lane & 16) ? 16 : 0));
    unsigned boff = sb + (unsigned)(BH0 + (n0w + (lane & 7) + ((lane & 8) ? 8 : 0)) * PAB
                                    + ((lane & 16) ? 16 : 0));

    for (int ch = 0; ch < 2; ++ch) {
        __syncthreads();
        for (int idx = tid; idx < 192 * 32; idx += 512) {
            int gg = idx >> 5, k4 = (idx & 31) * 4;
            float4 v = *(const float4*)(W + (size_t)(ch * 192 + gg) * HS + k4);
            ULL hi, lo; split4(v, hi, lo);
            int off = gg * PAB + k4 * 2;
            *(ULL*)(smc + BH0 + off) = hi;
            *(ULL*)(smc + BL0 + off) = lo;
        }
        __syncthreads();

        float acc[2][6][4];
#pragma unroll
        for (int rt = 0; rt < 2; ++rt)
#pragma unroll
            for (int nt = 0; nt < 6; ++nt)
#pragma unroll
                for (int q = 0; q < 4; ++q) acc[rt][nt][q] = 0.0f;

        for (int ks = 0; ks < 8; ++ks) {
            unsigned ah0[4], al0[4], ah1[4], al1[4];
            unsigned ka = aoff + ks * 32;
            ldsm4(ah0, ka);
            ldsm4(al0, ka + AL0);
            ldsm4(ah1, ka + 16 * PAB);
            ldsm4(al1, ka + 16 * PAB + AL0);
#pragma unroll
            for (int p = 0; p < 3; ++p) {
                unsigned bh[4], bl[4];
                unsigned kb = boff + p * 16 * PAB + ks * 32;
                ldsm4(bh, kb);
                ldsm4(bl, kb + (BL0 - BH0));
                mma16816(acc[0][2*p],   ah0, bh[0], bh[2]);
                mma16816(acc[0][2*p],   ah0, bl[0], bl[2]);
                mma16816(acc[0][2*p],   al0, bh[0], bh[2]);
                mma16816(acc[0][2*p+1], ah0, bh[1], bh[3]);
                mma16816(acc[0][2*p+1], ah0, bl[1], bl[3]);
                mma16816(acc[0][2*p+1], al0, bh[1], bh[3]);
                mma16816(acc[1][2*p],   ah1, bh[0], bh[2]);
                mma16816(acc[1][2*p],   ah1, bl[0], bl[2]);
                mma16816(acc[1][2*p],   al1, bh[0], bh[2]);
                mma16816(acc[1][2*p+1], ah1, bh[1], bh[3]);
                mma16816(acc[1][2*p+1], ah1, bl[1], bl[3]);
                mma16816(acc[1][2*p+1], al1, bh[1], bh[3]);
            }
        }

        int gb = ch * 192 + n0w;
        size_t rA = row0 + m0 + (lane >> 2);
#pragma unroll
        for (int rt = 0; rt < 2; ++rt) {
#pragma unroll
            for (int nt = 0; nt < 6; ++nt) {
                int col = gb + nt * 8 + (lane & 3) * 2;
                float2 bv = *(const float2*)(bih + col);
                float* p0 = g_gi + (rA + rt * 16) * G3 + col;
                *(float2*)p0 = make_float2(acc[rt][nt][0] + bv.x, acc[rt][nt][1] + bv.y);
                *(float2*)(p0 + 8 * G3) =
                    make_float2(acc[rt][nt][2] + bv.x, acc[rt][nt][3] + bv.y);
            }
        }
    }
}

// ---------------------------------------------------------------------------
// HMMA gi GEMM layer 0 (K=64, embedding fused) — verified R15 kernel.
// ---------------------------------------------------------------------------
constexpr int P64 = 144;
constexpr int A64L = 18432, B64H = 36864, B64L = 92160;
constexpr int SMEM_M64 = 147456;

__global__ __launch_bounds__(512) void gi_mma64(
    const float* __restrict__ Wih, const float* __restrict__ bih,
    const float* __restrict__ x,   const float* __restrict__ pea,
    const float* __restrict__ pet, const float* __restrict__ embW,
    const float* __restrict__ embB)
{
    extern __shared__ char smc[];
    unsigned sb = smem_u32(smc);
    int tid = threadIdx.x, warp = tid >> 5, lane = tid & 31;
    size_t row0 = (size_t)blockIdx.x * 128;

    for (int idx = tid; idx < 128 * 16; idx += 512) {
        int r = idx >> 4, kq = idx & 15;
        int row = (int)row0 + r;
        int t = row % Tt;
        int n = (row / Tt) & 7;
        float pe = __ldg(pet + t) + __ldg(pea + n);
        float2 xv = *(const float2*)(x + (size_t)row * 2);
        float x0 = xv.x + pe, x1 = xv.y + pe;
        float4 w0 = __ldg((const float4*)(embW + 8 * kq));
        float4 w1 = __ldg((const float4*)(embW + 8 * kq + 4));
        float4 b4 = __ldg((const float4*)(embB + 4 * kq));
        float4 v;
        v.x = fmaxf(fmaf(x0, w0.x, fmaf(x1, w0.y, b4.x)), 0.0f);
        v.y = fmaxf(fmaf(x0, w0.z, fmaf(x1, w0.w, b4.y)), 0.0f);
        v.z = fmaxf(fmaf(x0, w1.x, fmaf(x1, w1.y, b4.z)), 0.0f);
        v.w = fmaxf(fmaf(x0, w1.z, fmaf(x1, w1.w, b4.w)), 0.0f);
        ULL hi, lo; split4(v, hi, lo);
        int off = r * P64 + kq * 8;
        *(ULL*)(smc + off) = hi;
        *(ULL*)(smc + A64L + off) = lo;
    }
    for (int idx = tid; idx < 384 * 16; idx += 512) {
        int g = idx >> 4, kq = idx & 15;
        float4 v = *(const float4*)(Wih + (size_t)g * 64 + kq * 4);
        ULL hi, lo; split4(v, hi, lo);
        int off = g * P64 + kq * 8;
        *(ULL*)(smc + B64H + off) = hi;
        *(ULL*)(smc + B64L + off) = lo;
    }
    __syncthreads();

    int m0  = (warp >> 2) * 32;
    int n0w = (warp & 3) * 48;
    int lr  = (lane & 7) + ((lane & 8) ? 8 : 0);
    unsigned lo16 = (lane & 16) ? 16u : 0u;
    unsigned aoff = sb + (unsigned)((m0 + lr) * P64) + lo16;
    unsigned boff = sb + (unsigned)(B64H + (n0w + lr) * P64) + lo16;

    for (int ch = 0; ch < 2; ++ch) {
        float acc[2][6][4];
#pragma unroll
        for (int rt = 0; rt < 2; ++rt)
#pragma unroll
            for (int nt = 0; nt < 6; ++nt)
#pragma unroll
                for (int q = 0; q < 4; ++q) acc[rt][nt][q] = 0.0f;

#pragma unroll
        for (int ks = 0; ks < 4; ++ks) {
            unsigned ah0[4], al0[4], ah1[4], al1[4];
            unsigned ka = aoff + ks * 32;
            ldsm4(ah0, ka);
            ldsm4(al0, ka + A64L);
            ldsm4(ah1, ka + 16 * P64);
            ldsm4(al1, ka + 16 * P64 + A64L);
#pragma unroll
            for (int p = 0; p < 3; ++p) {
                unsigned bh[4], bl[4];
                unsigned kb = boff + (unsigned)(ch * 192 * P64 + p * 16 * P64) + ks * 32;
                ldsm4(bh, kb);
                ldsm4(bl, kb + (B64L - B64H));
                mma16816(acc[0][2*p],   ah0, bh[0], bh[2]);
                mma16816(acc[0][2*p],   ah0, bl[0], bl[2]);
                mma16816(acc[0][2*p],   al0, bh[0], bh[2]);
                mma16816(acc[0][2*p+1], ah0, bh[1], bh[3]);
                mma16816(acc[0][2*p+1], ah0, bl[1], bl[3]);
                mma16816(acc[0][2*p+1], al0, bh[1], bh[3]);
                mma16816(acc[1][2*p],   ah1, bh[0], bh[2]);
                mma16816(acc[1][2*p],   ah1, bl[0], bl[2]);
                mma16816(acc[1][2*p],   al1, bh[0], bh[2]);
                mma16816(acc[1][2*p+1], ah1, bh[1], bh[3]);
                mma16816(acc[1][2*p+1], ah1, bl[1], bl[3]);
                mma16816(acc[1][2*p+1], al1, bh[1], bh[3]);
            }
        }

        int gb = ch * 192 + n0w;
        size_t rA = row0 + m0 + (lane >> 2);
#pragma unroll
        for (int rt = 0; rt < 2; ++rt) {
#pragma unroll
            for (int nt = 0; nt < 6; ++nt) {
                int col = gb + nt * 8 + (lane & 3) * 2;
                float2 bv = *(const float2*)(bih + col);
                float* p0 = g_gi + (rA + rt * 16) * G3 + col;
                *(float2*)p0 = make_float2(acc[rt][nt][0] + bv.x, acc[rt][nt][1] + bv.y);
                *(float2*)(p0 + 8 * G3) =
                    make_float2(acc[rt][nt][2] + bv.x, acc[rt][nt][3] + bv.y);
            }
        }
    }
}

// ---------------------------------------------------------------------------
// HMMA GRU scan — exact R14 version (561 us/layer measured). gi loads stay in
// the update phase: no extra register pressure, no spills.
// ---------------------------------------------------------------------------
constexpr int WH0 = 0, WL0 = 98304, HH0 = 196608, HDL = 17408;
constexpr int SMEM_SCM = 231424;

__global__ __launch_bounds__(512) void scan_mma(
    const float* __restrict__ Whh, const float* __restrict__ bhh,
    float* __restrict__ hid)
{
    extern __shared__ char smc[];
    unsigned sb = smem_u32(smc);
    int tid = threadIdx.x, warp = tid >> 5, lane = tid & 31;
    int m0 = blockIdx.x * 64;

    for (int idx = tid; idx < 384 * 16; idx += 512) {
        int g = idx >> 4, c = idx & 15;
        const float* src = Whh + (size_t)g * HS + c * 8;
        float4 v0 = *(const float4*)(src);
        float4 v1 = *(const float4*)(src + 4);
        ULL h0, l0, h1, l1;
        split4(v0, h0, l0);
        split4(v1, h1, l1);
        int sw = g * 256 + ((c ^ (g & 7)) << 4);
        *(ULL*)(smc + WH0 + sw)     = h0;
        *(ULL*)(smc + WH0 + sw + 8) = h1;
        *(ULL*)(smc + WL0 + sw)     = l0;
        *(ULL*)(smc + WL0 + sw + 8) = l1;
    }
    for (int i = tid; i < 8704; i += 512) ((unsigned*)(smc + HH0))[i] = 0u;

    int rh2 = warp >> 3;
    int wg  = warp & 7;
    int lr   = (lane & 7) + ((lane & 8) ? 8 : 0);
    int c0   = (lane & 16) ? 1 : 0;
    unsigned abase = sb + (unsigned)(HH0 + (rh2 * 32 + lr) * PAB + c0 * 16);
    int grow = wg * 16 + lr;
    unsigned bRow = sb + (unsigned)(grow * 256);
    int rx = grow & 7;

    int cq = (lane & 3) * 2;
    int rq = lane >> 2;

    float2 biR[2], biZ[2], biN[2];
#pragma unroll
    for (int nt = 0; nt < 2; ++nt) {
        int c = wg * 16 + nt * 8 + cq;
        biR[nt] = *(const float2*)(bhh + c);
        biZ[nt] = *(const float2*)(bhh + 128 + c);
        biN[nt] = *(const float2*)(bhh + 256 + c);
    }

    float2 hreg[2][2][2];
#pragma unroll
    for (int a = 0; a < 2; ++a)
#pragma unroll
        for (int b = 0; b < 2; ++b)
#pragma unroll
            for (int c = 0; c < 2; ++c) hreg[a][b][c] = make_float2(0.0f, 0.0f);

    __syncthreads();

    for (int t = 0; t < Tt; ++t) {
        float acc[2][3][2][4];
#pragma unroll
        for (int a = 0; a < 2; ++a)
#pragma unroll
            for (int s = 0; s < 3; ++s)
#pragma unroll
                for (int n = 0; n < 2; ++n)
#pragma unroll
                    for (int q = 0; q < 4; ++q) acc[a][s][n][q] = 0.0f;

        for (int ks = 0; ks < 8; ++ks) {
            unsigned ka = abase + ks * 32;
            unsigned ah0[4], al0[4], ah1[4], al1[4];
            ldsm4(ah0, ka);
            ldsm4(al0, ka + HDL);
            ldsm4(ah1, ka + 16 * PAB);
            ldsm4(al1, ka + 16 * PAB + HDL);
            unsigned ch = (unsigned)(((2 * ks + c0) ^ rx) << 4);
#pragma unroll
            for (int s = 0; s < 3; ++s) {
                unsigned kb = bRow + (unsigned)(s * 128 * 256) + ch;
                unsigned bh[4], bl[4];
                ldsm4(bh, kb);
                ldsm4(bl, kb + (unsigned)WL0);
                mma16816(acc[0][s][0], ah0, bh[0], bh[2]);
                mma16816(acc[0][s][0], ah0, bl[0], bl[2]);
                mma16816(acc[0][s][0], al0, bh[0], bh[2]);
                mma16816(acc[0][s][1], ah0, bh[1], bh[3]);
                mma16816(acc[0][s][1], ah0, bl[1], bl[3]);
                mma16816(acc[0][s][1], al0, bh[1], bh[3]);
                mma16816(acc[1][s][0], ah1, bh[0], bh[2]);
                mma16816(acc[1][s][0], ah1, bl[0], bl[2]);
                mma16816(acc[1][s][0], al1, bh[0], bh[2]);
                mma16816(acc[1][s][1], ah1, bh[1], bh[3]);
                mma16816(acc[1][s][1], ah1, bl[1], bl[3]);
                mma16816(acc[1][s][1], al1, bh[1], bh[3]);
            }
        }
        __syncthreads();

#pragma unroll
        for (int mt = 0; mt < 2; ++mt)
#pragma unroll
        for (int rh = 0; rh < 2; ++rh)
#pragma unroll
        for (int nt = 0; nt < 2; ++nt) {
            int m = rh2 * 32 + mt * 16 + rh * 8 + rq;
            int c = wg * 16 + nt * 8 + cq;
            size_t rbase = (size_t)(m0 + m) * Tt + t;
            const float* gp = g_gi + rbase * G3;
            float2 giR = *(const float2*)(gp + c);
            float2 giZ = *(const float2*)(gp + 128 + c);
            float2 giN = *(const float2*)(gp + 256 + c);
            float ghR0 = acc[mt][0][nt][rh*2], ghR1 = acc[mt][0][nt][rh*2+1];
            float ghZ0 = acc[mt][1][nt][rh*2], ghZ1 = acc[mt][1][nt][rh*2+1];
            float ghN0 = acc[mt][2][nt][rh*2], ghN1 = acc[mt][2][nt][rh*2+1];
            float rv0 = sigm(giR.x + ghR0 + biR[nt].x);
            float rv1 = sigm(giR.y + ghR1 + biR[nt].y);
            float zv0 = sigm(giZ.x + ghZ0 + biZ[nt].x);
            float zv1 = sigm(giZ.y + ghZ1 + biZ[nt].y);
            float nv0 = tanh_(giN.x + rv0 * (ghN0 + biN[nt].x));
            float nv1 = tanh_(giN.y + rv1 * (ghN1 + biN[nt].y));
            float hn0 = (1.0f - zv0) * nv0 + zv0 * hreg[mt][rh][nt].x;
            float hn1 = (1.0f - zv1) * nv1 + zv1 * hreg[mt][rh][nt].y;
            hreg[mt][rh][nt] = make_float2(hn0, hn1);
            *(float2*)(g_ys + rbase * HS + c) = hreg[mt][rh][nt];
            unsigned short l0v, l1v;
            unsigned short h0v = split1(hn0, l0v);
            unsigned short h1v = split1(hn1, l1v);
            int off = m * PAB + c * 2;
            *(unsigned*)(smc + HH0 + off)       = (unsigned)h0v | ((unsigned)h1v << 16);
            *(unsigned*)(smc + HH0 + HDL + off) = (unsigned)l0v | ((unsigned)l1v << 16);
        }
        __syncthreads();
    }

    if (rq == 7) {
#pragma unroll
        for (int mt = 0; mt < 2; ++mt)
#pragma unroll
        for (int rh = 0; rh < 2; ++rh)
#pragma unroll
        for (int nt = 0; nt < 2; ++nt) {
            int m = rh2 * 32 + mt * 16 + rh * 8 + 7;
            int b = (m0 + m) >> 3;
            int c = wg * 16 + nt * 8 + cq;
            *(float2*)(hid + (size_t)b * HS + c) = hreg[mt][rh][nt];
        }
    }
}

// ---------------------------------------------------------------------------
__global__ __launch_bounds__(256) void out_kernel(
    const float* __restrict__ oW, const float* __restrict__ ob,
    float* __restrict__ out)
{
    __shared__ float sW[128 * 64];
    int tid = threadIdx.x;
    for (int idx = tid; idx < 64 * 128; idx += 256) {
        int e = idx >> 7, k = idx & 127;
        sW[k * 64 + e] = oW[idx];
    }
    __syncthreads();
    int gid = blockIdx.x * 256 + tid;
    int e = gid & 63;
    int m = gid >> 6;
    const float* ys = g_ys + ((size_t)m * Tt + (Tt - 1)) * HS;
    float acc = ob[e];
#pragma unroll 8
    for (int k = 0; k < 128; ++k) acc = fmaf(ys[k], sW[k * 64 + e], acc);
    out[gid] = acc;
}

// ---------------------------------------------------------------------------
extern "C" void kernel_launch(void* const* d_in, const int* in_sizes, int n_in,
                              void* d_out, int out_size) {
    const float* x    = (const float*)d_in[0];
    const float* pea  = (const float*)d_in[1];
    const float* pet  = (const float*)d_in[2];
    const float* embW = (const float*)d_in[3];
    const float* embB = (const float*)d_in[4];
    const float* Wih0 = (const float*)d_in[5];
    const float* WihR = (const float*)d_in[6];
    const float* Whh  = (const float*)d_in[7];
    const float* bih  = (const float*)d_in[8];
    const float* bhh  = (const float*)d_in[9];
    const float* outW = (const float*)d_in[10];
    const float* outB = (const float*)d_in[11];

    float* out = (float*)d_out;
    float* hid = out + OUT0;

    cudaFuncSetAttribute(gi_mma64, cudaFuncAttributeMaxDynamicSharedMemorySize, SMEM_M64);
    cudaFuncSetAttribute(gi_mma,   cudaFuncAttributeMaxDynamicSharedMemorySize, SMEM_MMA);
    cudaFuncSetAttribute(scan_mma, cudaFuncAttributeMaxDynamicSharedMemorySize, SMEM_SCM);

    gi_mma64<<<RT / 128, 512, SMEM_M64>>>(Wih0, bih, x, pea, pet, embW, embB);
    scan_mma<<<Mm / 64, 512, SMEM_SCM>>>(Whh, bhh, hid);

    gi_mma<<<RT / 128, 512, SMEM_MMA>>>(WihR, bih + G3);
    scan_mma<<<Mm / 64, 512, SMEM_SCM>>>(Whh + (size_t)G3 * HS, bhh + G3,
                                         hid + (size_t)Bb * HS);

    gi_mma<<<RT / 128, 512, SMEM_MMA>>>(WihR + (size_t)G3 * HS, bih + 2 * G3);
    scan_mma<<<Mm / 64, 512, SMEM_SCM>>>(Whh + (size_t)2 * G3 * HS, bhh + 2 * G3,
                                         hid + (size_t)2 * Bb * HS);

    out_kernel<<<(Mm * 64) / 256, 256>>>(outW, outB, out);
}

// round 17
// speedup vs baseline: 1.3222x; 1.0426x over previous
#include <cuda_runtime.h>
#include <cuda_bf16.h>

constexpr int Bb  = 2048;
constexpr int Tt  = 20;
constexpr int Mm  = 16384;
constexpr int HS  = 128;
constexpr int G3  = 384;
constexpr int RT  = Mm * Tt;        // 327680
constexpr int OUT0 = Mm * 64;

__device__ float g_gi[(size_t)RT * G3];
__device__ float g_ys[(size_t)RT * HS];

typedef unsigned long long ULL;

__device__ __forceinline__ float sigm(float x) { return 1.0f / (1.0f + __expf(-x)); }
__device__ __forceinline__ float tanh_(float x) { return 1.0f - 2.0f / (__expf(2.0f * x) + 1.0f); }

__device__ __forceinline__ unsigned smem_u32(const void* p) {
    unsigned a;
    asm("{ .reg .u64 t; cvta.to.shared.u64 t, %1; cvt.u32.u64 %0, t; }" : "=r"(a) : "l"(p));
    return a;
}
__device__ __forceinline__ void ldsm4(unsigned* r, unsigned addr) {
    asm volatile("ldmatrix.sync.aligned.m8n8.x4.shared.b16 {%0,%1,%2,%3}, [%4];"
        : "=r"(r[0]), "=r"(r[1]), "=r"(r[2]), "=r"(r[3]) : "r"(addr));
}
__device__ __forceinline__ void mma16816(float* c, const unsigned* a, unsigned b0, unsigned b1) {
    asm volatile("mma.sync.aligned.m16n8k16.row.col.f32.bf16.bf16.f32 "
        "{%0,%1,%2,%3}, {%4,%5,%6,%7}, {%8,%9}, {%0,%1,%2,%3};"
        : "+f"(c[0]), "+f"(c[1]), "+f"(c[2]), "+f"(c[3])
        : "r"(a[0]), "r"(a[1]), "r"(a[2]), "r"(a[3]), "r"(b0), "r"(b1));
}

__device__ __forceinline__ void split4(float4 v, ULL& hi, ULL& lo) {
    float a[4] = {v.x, v.y, v.z, v.w};
    unsigned short hs[4], ls[4];
#pragma unroll
    for (int i = 0; i < 4; ++i) {
        __nv_bfloat16 h = __float2bfloat16(a[i]);
        hs[i] = ((__nv_bfloat16_raw)h).x;
        __nv_bfloat16 l = __float2bfloat16(a[i] - __bfloat162float(h));
        ls[i] = ((__nv_bfloat16_raw)l).x;
    }
    hi = (ULL)hs[0] | ((ULL)hs[1] << 16) | ((ULL)hs[2] << 32) | ((ULL)hs[3] << 48);
    lo = (ULL)ls[0] | ((ULL)ls[1] << 16) | ((ULL)ls[2] << 32) | ((ULL)ls[3] << 48);
}
__device__ __forceinline__ unsigned split1(float x, unsigned short& lo) {
    __nv_bfloat16 h = __float2bfloat16(x);
    lo = ((__nv_bfloat16_raw)__float2bfloat16(x - __bfloat162float(h))).x;
    return ((__nv_bfloat16_raw)h).x;
}

// ---------------------------------------------------------------------------
// HMMA gi GEMM (layers 1,2) — verified R12/R13 kernel, unchanged.
// ---------------------------------------------------------------------------
constexpr int PAB = 272;
constexpr int AH0 = 0, AL0 = 34816, BH0 = 69632, BL0 = 121856;
constexpr int SMEM_MMA = 174080;

__global__ __launch_bounds__(512) void gi_mma(
    const float* __restrict__ W, const float* __restrict__ bih)
{
    extern __shared__ char smc[];
    unsigned sb = smem_u32(smc);
    int tid = threadIdx.x, warp = tid >> 5, lane = tid & 31;
    size_t row0 = (size_t)blockIdx.x * 128;

    for (int idx = tid; idx < 128 * 32; idx += 512) {
        int r = idx >> 5, k4 = (idx & 31) * 4;
        float4 v = *(const float4*)(g_ys + (row0 + r) * HS + k4);
        ULL hi, lo; split4(v, hi, lo);
        int off = r * PAB + k4 * 2;
        *(ULL*)(smc + AH0 + off) = hi;
        *(ULL*)(smc + AL0 + off) = lo;
    }

    int m0  = (warp >> 2) * 32;
    int n0w = (warp & 3) * 48;
    unsigned aoff = sb + (unsigned)((m0 + (lane & 7) + ((lane & 8) ? 8 : 0)) * PAB
                                    + ((lane & 16) ? 16 : 0));
    unsigned boff = sb + (unsigned)(BH0 + (n0w + (lane & 7) + ((lane & 8) ? 8 : 0)) * PAB
                                    + ((lane & 16) ? 16 : 0));

    for (int ch = 0; ch < 2; ++ch) {
        __syncthreads();
        for (int idx = tid; idx < 192 * 32; idx += 512) {
            int gg = idx >> 5, k4 = (idx & 31) * 4;
            float4 v = *(const float4*)(W + (size_t)(ch * 192 + gg) * HS + k4);
            ULL hi, lo; split4(v, hi, lo);
            int off = gg * PAB + k4 * 2;
            *(ULL*)(smc + BH0 + off) = hi;
            *(ULL*)(smc + BL0 + off) = lo;
        }
        __syncthreads();

        float acc[2][6][4];
#pragma unroll
        for (int rt = 0; rt < 2; ++rt)
#pragma unroll
            for (int nt = 0; nt < 6; ++nt)
#pragma unroll
                for (int q = 0; q < 4; ++q) acc[rt][nt][q] = 0.0f;

        for (int ks = 0; ks < 8; ++ks) {
            unsigned ah0[4], al0[4], ah1[4], al1[4];
            unsigned ka = aoff + ks * 32;
            ldsm4(ah0, ka);
            ldsm4(al0, ka + AL0);
            ldsm4(ah1, ka + 16 * PAB);
            ldsm4(al1, ka + 16 * PAB + AL0);
#pragma unroll
            for (int p = 0; p < 3; ++p) {
                unsigned bh[4], bl[4];
                unsigned kb = boff + p * 16 * PAB + ks * 32;
                ldsm4(bh, kb);
                ldsm4(bl, kb + (BL0 - BH0));
                mma16816(acc[0][2*p],   ah0, bh[0], bh[2]);
                mma16816(acc[0][2*p],   ah0, bl[0], bl[2]);
                mma16816(acc[0][2*p],   al0, bh[0], bh[2]);
                mma16816(acc[0][2*p+1], ah0, bh[1], bh[3]);
                mma16816(acc[0][2*p+1], ah0, bl[1], bl[3]);
                mma16816(acc[0][2*p+1], al0, bh[1], bh[3]);
                mma16816(acc[1][2*p],   ah1, bh[0], bh[2]);
                mma16816(acc[1][2*p],   ah1, bl[0], bl[2]);
                mma16816(acc[1][2*p],   al1, bh[0], bh[2]);
                mma16816(acc[1][2*p+1], ah1, bh[1], bh[3]);
                mma16816(acc[1][2*p+1], ah1, bl[1], bl[3]);
                mma16816(acc[1][2*p+1], al1, bh[1], bh[3]);
            }
        }

        int gb = ch * 192 + n0w;
        size_t rA = row0 + m0 + (lane >> 2);
#pragma unroll
        for (int rt = 0; rt < 2; ++rt) {
#pragma unroll
            for (int nt = 0; nt < 6; ++nt) {
                int col = gb + nt * 8 + (lane & 3) * 2;
                float2 bv = *(const float2*)(bih + col);
                float* p0 = g_gi + (rA + rt * 16) * G3 + col;
                *(float2*)p0 = make_float2(acc[rt][nt][0] + bv.x, acc[rt][nt][1] + bv.y);
                *(float2*)(p0 + 8 * G3) =
                    make_float2(acc[rt][nt][2] + bv.x, acc[rt][nt][3] + bv.y);
            }
        }
    }
}

// ---------------------------------------------------------------------------
// HMMA gi GEMM layer 0 (K=64, embedding fused) — verified R15 kernel.
// ---------------------------------------------------------------------------
constexpr int P64 = 144;
constexpr int A64L = 18432, B64H = 36864, B64L = 92160;
constexpr int SMEM_M64 = 147456;

__global__ __launch_bounds__(512) void gi_mma64(
    const float* __restrict__ Wih, const float* __restrict__ bih,
    const float* __restrict__ x,   const float* __restrict__ pea,
    const float* __restrict__ pet, const float* __restrict__ embW,
    const float* __restrict__ embB)
{
    extern __shared__ char smc[];
    unsigned sb = smem_u32(smc);
    int tid = threadIdx.x, warp = tid >> 5, lane = tid & 31;
    size_t row0 = (size_t)blockIdx.x * 128;

    for (int idx = tid; idx < 128 * 16; idx += 512) {
        int r = idx >> 4, kq = idx & 15;
        int row = (int)row0 + r;
        int t = row % Tt;
        int n = (row / Tt) & 7;
        float pe = __ldg(pet + t) + __ldg(pea + n);
        float2 xv = *(const float2*)(x + (size_t)row * 2);
        float x0 = xv.x + pe, x1 = xv.y + pe;
        float4 w0 = __ldg((const float4*)(embW + 8 * kq));
        float4 w1 = __ldg((const float4*)(embW + 8 * kq + 4));
        float4 b4 = __ldg((const float4*)(embB + 4 * kq));
        float4 v;
        v.x = fmaxf(fmaf(x0, w0.x, fmaf(x1, w0.y, b4.x)), 0.0f);
        v.y = fmaxf(fmaf(x0, w0.z, fmaf(x1, w0.w, b4.y)), 0.0f);
        v.z = fmaxf(fmaf(x0, w1.x, fmaf(x1, w1.y, b4.z)), 0.0f);
        v.w = fmaxf(fmaf(x0, w1.z, fmaf(x1, w1.w, b4.w)), 0.0f);
        ULL hi, lo; split4(v, hi, lo);
        int off = r * P64 + kq * 8;
        *(ULL*)(smc + off) = hi;
        *(ULL*)(smc + A64L + off) = lo;
    }
    for (int idx = tid; idx < 384 * 16; idx += 512) {
        int g = idx >> 4, kq = idx & 15;
        float4 v = *(const float4*)(Wih + (size_t)g * 64 + kq * 4);
        ULL hi, lo; split4(v, hi, lo);
        int off = g * P64 + kq * 8;
        *(ULL*)(smc + B64H + off) = hi;
        *(ULL*)(smc + B64L + off) = lo;
    }
    __syncthreads();

    int m0  = (warp >> 2) * 32;
    int n0w = (warp & 3) * 48;
    int lr  = (lane & 7) + ((lane & 8) ? 8 : 0);
    unsigned lo16 = (lane & 16) ? 16u : 0u;
    unsigned aoff = sb + (unsigned)((m0 + lr) * P64) + lo16;
    unsigned boff = sb + (unsigned)(B64H + (n0w + lr) * P64) + lo16;

    for (int ch = 0; ch < 2; ++ch) {
        float acc[2][6][4];
#pragma unroll
        for (int rt = 0; rt < 2; ++rt)
#pragma unroll
            for (int nt = 0; nt < 6; ++nt)
#pragma unroll
                for (int q = 0; q < 4; ++q) acc[rt][nt][q] = 0.0f;

#pragma unroll
        for (int ks = 0; ks < 4; ++ks) {
            unsigned ah0[4], al0[4], ah1[4], al1[4];
            unsigned ka = aoff + ks * 32;
            ldsm4(ah0, ka);
            ldsm4(al0, ka + A64L);
            ldsm4(ah1, ka + 16 * P64);
            ldsm4(al1, ka + 16 * P64 + A64L);
#pragma unroll
            for (int p = 0; p < 3; ++p) {
                unsigned bh[4], bl[4];
                unsigned kb = boff + (unsigned)(ch * 192 * P64 + p * 16 * P64) + ks * 32;
                ldsm4(bh, kb);
                ldsm4(bl, kb + (B64L - B64H));
                mma16816(acc[0][2*p],   ah0, bh[0], bh[2]);
                mma16816(acc[0][2*p],   ah0, bl[0], bl[2]);
                mma16816(acc[0][2*p],   al0, bh[0], bh[2]);
                mma16816(acc[0][2*p+1], ah0, bh[1], bh[3]);
                mma16816(acc[0][2*p+1], ah0, bl[1], bl[3]);
                mma16816(acc[0][2*p+1], al0, bh[1], bh[3]);
                mma16816(acc[1][2*p],   ah1, bh[0], bh[2]);
                mma16816(acc[1][2*p],   ah1, bl[0], bl[2]);
                mma16816(acc[1][2*p],   al1, bh[0], bh[2]);
                mma16816(acc[1][2*p+1], ah1, bh[1], bh[3]);
                mma16816(acc[1][2*p+1], ah1, bl[1], bl[3]);
                mma16816(acc[1][2*p+1], al1, bh[1], bh[3]);
            }
        }

        int gb = ch * 192 + n0w;
        size_t rA = row0 + m0 + (lane >> 2);
#pragma unroll
        for (int rt = 0; rt < 2; ++rt) {
#pragma unroll
            for (int nt = 0; nt < 6; ++nt) {
                int col = gb + nt * 8 + (lane & 3) * 2;
                float2 bv = *(const float2*)(bih + col);
                float* p0 = g_gi + (rA + rt * 16) * G3 + col;
                *(float2*)p0 = make_float2(acc[rt][nt][0] + bv.x, acc[rt][nt][1] + bv.y);
                *(float2*)(p0 + 8 * G3) =
                    make_float2(acc[rt][nt][2] + bv.x, acc[rt][nt][3] + bv.y);
            }
        }
    }
}

// ---------------------------------------------------------------------------
// HMMA GRU scan — R14/R16 kernel + gi L2 prefetch (zero-register) and
// optional ys-store suppression (last layer writes only t == Tt-1).
// ---------------------------------------------------------------------------
constexpr int WH0 = 0, WL0 = 98304, HH0 = 196608, HDL = 17408;
constexpr int SMEM_SCM = 231424;

__global__ __launch_bounds__(512) void scan_mma(
    const float* __restrict__ Whh, const float* __restrict__ bhh,
    float* __restrict__ hid, int writeAll)
{
    extern __shared__ char smc[];
    unsigned sb = smem_u32(smc);
    int tid = threadIdx.x, warp = tid >> 5, lane = tid & 31;
    int m0 = blockIdx.x * 64;

    for (int idx = tid; idx < 384 * 16; idx += 512) {
        int g = idx >> 4, c = idx & 15;
        const float* src = Whh + (size_t)g * HS + c * 8;
        float4 v0 = *(const float4*)(src);
        float4 v1 = *(const float4*)(src + 4);
        ULL h0, l0, h1, l1;
        split4(v0, h0, l0);
        split4(v1, h1, l1);
        int sw = g * 256 + ((c ^ (g & 7)) << 4);
        *(ULL*)(smc + WH0 + sw)     = h0;
        *(ULL*)(smc + WH0 + sw + 8) = h1;
        *(ULL*)(smc + WL0 + sw)     = l0;
        *(ULL*)(smc + WL0 + sw + 8) = l1;
    }
    for (int i = tid; i < 8704; i += 512) ((unsigned*)(smc + HH0))[i] = 0u;

    int rh2 = warp >> 3;
    int wg  = warp & 7;
    int lr   = (lane & 7) + ((lane & 8) ? 8 : 0);
    int c0   = (lane & 16) ? 1 : 0;
    unsigned abase = sb + (unsigned)(HH0 + (rh2 * 32 + lr) * PAB + c0 * 16);
    int grow = wg * 16 + lr;
    unsigned bRow = sb + (unsigned)(grow * 256);
    int rx = grow & 7;

    int cq = (lane & 3) * 2;
    int rq = lane >> 2;

    float2 biR[2], biZ[2], biN[2];
#pragma unroll
    for (int nt = 0; nt < 2; ++nt) {
        int c = wg * 16 + nt * 8 + cq;
        biR[nt] = *(const float2*)(bhh + c);
        biZ[nt] = *(const float2*)(bhh + 128 + c);
        biN[nt] = *(const float2*)(bhh + 256 + c);
    }

    float2 hreg[2][2][2];
#pragma unroll
    for (int a = 0; a < 2; ++a)
#pragma unroll
        for (int b = 0; b < 2; ++b)
#pragma unroll
            for (int c = 0; c < 2; ++c) hreg[a][b][c] = make_float2(0.0f, 0.0f);

    __syncthreads();

    for (int t = 0; t < Tt; ++t) {
        // gi L2 prefetch (fire-and-forget, no registers held): by the time the
        // update phase issues the real LDGs, lines are in L2 (~250 vs ~600 cyc).
#pragma unroll
        for (int mt = 0; mt < 2; ++mt)
#pragma unroll
        for (int rh = 0; rh < 2; ++rh) {
            int m = rh2 * 32 + mt * 16 + rh * 8 + rq;
            const float* gp = g_gi + ((size_t)(m0 + m) * Tt + t) * G3 + wg * 16 + cq;
            asm volatile("prefetch.global.L2 [%0];" :: "l"(gp));
            asm volatile("prefetch.global.L2 [%0];" :: "l"(gp + 128));
            asm volatile("prefetch.global.L2 [%0];" :: "l"(gp + 256));
        }

        float acc[2][3][2][4];
#pragma unroll
        for (int a = 0; a < 2; ++a)
#pragma unroll
            for (int s = 0; s < 3; ++s)
#pragma unroll
                for (int n = 0; n < 2; ++n)
#pragma unroll
                    for (int q = 0; q < 4; ++q) acc[a][s][n][q] = 0.0f;

        for (int ks = 0; ks < 8; ++ks) {
            unsigned ka = abase + ks * 32;
            unsigned ah0[4], al0[4], ah1[4], al1[4];
            ldsm4(ah0, ka);
            ldsm4(al0, ka + HDL);
            ldsm4(ah1, ka + 16 * PAB);
            ldsm4(al1, ka + 16 * PAB + HDL);
            unsigned ch = (unsigned)(((2 * ks + c0) ^ rx) << 4);
#pragma unroll
            for (int s = 0; s < 3; ++s) {
                unsigned kb = bRow + (unsigned)(s * 128 * 256) + ch;
                unsigned bh[4], bl[4];
                ldsm4(bh, kb);
                ldsm4(bl, kb + (unsigned)WL0);
                mma16816(acc[0][s][0], ah0, bh[0], bh[2]);
                mma16816(acc[0][s][0], ah0, bl[0], bl[2]);
                mma16816(acc[0][s][0], al0, bh[0], bh[2]);
                mma16816(acc[0][s][1], ah0, bh[1], bh[3]);
                mma16816(acc[0][s][1], ah0, bl[1], bl[3]);
                mma16816(acc[0][s][1], al0, bh[1], bh[3]);
                mma16816(acc[1][s][0], ah1, bh[0], bh[2]);
                mma16816(acc[1][s][0], ah1, bl[0], bl[2]);
                mma16816(acc[1][s][0], al1, bh[0], bh[2]);
                mma16816(acc[1][s][1], ah1, bh[1], bh[3]);
                mma16816(acc[1][s][1], ah1, bl[1], bl[3]);
                mma16816(acc[1][s][1], al1, bh[1], bh[3]);
            }
        }
        __syncthreads();

        int doWrite = writeAll | (t == Tt - 1);
#pragma unroll
        for (int mt = 0; mt < 2; ++mt)
#pragma unroll
        for (int rh = 0; rh < 2; ++rh)
#pragma unroll
        for (int nt = 0; nt < 2; ++nt) {
            int m = rh2 * 32 + mt * 16 + rh * 8 + rq;
            int c = wg * 16 + nt * 8 + cq;
            size_t rbase = (size_t)(m0 + m) * Tt + t;
            const float* gp = g_gi + rbase * G3;
            float2 giR = *(const float2*)(gp + c);
            float2 giZ = *(const float2*)(gp + 128 + c);
            float2 giN = *(const float2*)(gp + 256 + c);
            float ghR0 = acc[mt][0][nt][rh*2], ghR1 = acc[mt][0][nt][rh*2+1];
            float ghZ0 = acc[mt][1][nt][rh*2], ghZ1 = acc[mt][1][nt][rh*2+1];
            float ghN0 = acc[mt][2][nt][rh*2], ghN1 = acc[mt][2][nt][rh*2+1];
            float rv0 = sigm(giR.x + ghR0 + biR[nt].x);
            float rv1 = sigm(giR.y + ghR1 + biR[nt].y);
            float zv0 = sigm(giZ.x + ghZ0 + biZ[nt].x);
            float zv1 = sigm(giZ.y + ghZ1 + biZ[nt].y);
            float nv0 = tanh_(giN.x + rv0 * (ghN0 + biN[nt].x));
            float nv1 = tanh_(giN.y + rv1 * (ghN1 + biN[nt].y));
            float hn0 = (1.0f - zv0) * nv0 + zv0 * hreg[mt][rh][nt].x;
            float hn1 = (1.0f - zv1) * nv1 + zv1 * hreg[mt][rh][nt].y;
            hreg[mt][rh][nt] = make_float2(hn0, hn1);
            if (doWrite)
                *(float2*)(g_ys + rbase * HS + c) = hreg[mt][rh][nt];
            unsigned short l0v, l1v;
            unsigned short h0v = split1(hn0, l0v);
            unsigned short h1v = split1(hn1, l1v);
            int off = m * PAB + c * 2;
            *(unsigned*)(smc + HH0 + off)       = (unsigned)h0v | ((unsigned)h1v << 16);
            *(unsigned*)(smc + HH0 + HDL + off) = (unsigned)l0v | ((unsigned)l1v << 16);
        }
        __syncthreads();
    }

    if (rq == 7) {
#pragma unroll
        for (int mt = 0; mt < 2; ++mt)
#pragma unroll
        for (int rh = 0; rh < 2; ++rh)
#pragma unroll
        for (int nt = 0; nt < 2; ++nt) {
            int m = rh2 * 32 + mt * 16 + rh * 8 + 7;
            int b = (m0 + m) >> 3;
            int c = wg * 16 + nt * 8 + cq;
            *(float2*)(hid + (size_t)b * HS + c) = hreg[mt][rh][nt];
        }
    }
}

// ---------------------------------------------------------------------------
__global__ __launch_bounds__(256) void out_kernel(
    const float* __restrict__ oW, const float* __restrict__ ob,
    float* __restrict__ out)
{
    __shared__ float sW[128 * 64];
    int tid = threadIdx.x;
    for (int idx = tid; idx < 64 * 128; idx += 256) {
        int e = idx >> 7, k = idx & 127;
        sW[k * 64 + e] = oW[idx];
    }
    __syncthreads();
    int gid = blockIdx.x * 256 + tid;
    int e = gid & 63;
    int m = gid >> 6;
    const float* ys = g_ys + ((size_t)m * Tt + (Tt - 1)) * HS;
    float acc = ob[e];
#pragma unroll 8
    for (int k = 0; k < 128; ++k) acc = fmaf(ys[k], sW[k * 64 + e], acc);
    out[gid] = acc;
}

// ---------------------------------------------------------------------------
extern "C" void kernel_launch(void* const* d_in, const int* in_sizes, int n_in,
                              void* d_out, int out_size) {
    const float* x    = (const float*)d_in[0];
    const float* pea  = (const float*)d_in[1];
    const float* pet  = (const float*)d_in[2];
    const float* embW = (const float*)d_in[3];
    const float* embB = (const float*)d_in[4];
    const float* Wih0 = (const float*)d_in[5];
    const float* WihR = (const float*)d_in[6];
    const float* Whh  = (const float*)d_in[7];
    const float* bih  = (const float*)d_in[8];
    const float* bhh  = (const float*)d_in[9];
    const float* outW = (const float*)d_in[10];
    const float* outB = (const float*)d_in[11];

    float* out = (float*)d_out;
    float* hid = out + OUT0;

    cudaFuncSetAttribute(gi_mma64, cudaFuncAttributeMaxDynamicSharedMemorySize, SMEM_M64);
    cudaFuncSetAttribute(gi_mma,   cudaFuncAttributeMaxDynamicSharedMemorySize, SMEM_MMA);
    cudaFuncSetAttribute(scan_mma, cudaFuncAttributeMaxDynamicSharedMemorySize, SMEM_SCM);

    gi_mma64<<<RT / 128, 512, SMEM_M64>>>(Wih0, bih, x, pea, pet, embW, embB);
    scan_mma<<<Mm / 64, 512, SMEM_SCM>>>(Whh, bhh, hid, 1);

    gi_mma<<<RT / 128, 512, SMEM_MMA>>>(WihR, bih + G3);
    scan_mma<<<Mm / 64, 512, SMEM_SCM>>>(Whh + (size_t)G3 * HS, bhh + G3,
                                         hid + (size_t)Bb * HS, 1);

    gi_mma<<<RT / 128, 512, SMEM_MMA>>>(WihR + (size_t)G3 * HS, bih + 2 * G3);
    scan_mma<<<Mm / 64, 512, SMEM_SCM>>>(Whh + (size_t)2 * G3 * HS, bhh + 2 * G3,
                                         hid + (size_t)2 * Bb * HS, 0);

    out_kernel<<<(Mm * 64) / 256, 256>>>(outW, outB, out);
}